// round 5
// baseline (speedup 1.0000x reference)
#include <cuda_runtime.h>
#include <cstdint>

// Problem shape (fixed by the dataset): B=512, S=1024, T=64
#define Bn 512
#define Sn 1024
#define Tn 64
#define BPB 4   // batches per block (one per SMSP, handled by a warp PAIR)

typedef unsigned long long u64;

__device__ float g_z[Bn];
__device__ float g_sc[Bn];

__device__ __forceinline__ u64 ffma2(u64 a, u64 b, u64 c) {
    u64 d;
    asm("fma.rn.f32x2 %0, %1, %2, %3;" : "=l"(d) : "l"(a), "l"(b), "l"(c));
    return d;
}
__device__ __forceinline__ u64 fadd2(u64 a, u64 b) {
    u64 d;
    asm("add.rn.f32x2 %0, %1, %2;" : "=l"(d) : "l"(a), "l"(b));
    return d;
}
__device__ __forceinline__ u64 pk2(float a, float b) {
    u64 d;
    asm("mov.b64 %0, {%1,%2};" : "=l"(d) : "f"(a), "f"(b));
    return d;
}
__device__ __forceinline__ float2 upk(u64 p) {
    float2 r;
    asm("mov.b64 {%0,%1}, %2;" : "=f"(r.x), "=f"(r.y) : "l"(p));
    return r;
}

// ---------------------------------------------------------------------------
// Forward recursion, linear domain:
//   s_{t+1}[j] = (sum_i s_t[i] * E[i][j]) * exp(e_t[j]),  E = exp(trans)
// Block = 8 warps = 4 batches. Batch p is owned by the SYMMETRIC warp pair
// (p, p+4) — both land on SMSP p (wid%4), giving 2 warps per scheduler.
// Each warp owns 32 columns (1 column per thread, 32 FFMA2/step); both halves
// publish their s half and re-read the full vector after one block barrier.
// No cross-warp arithmetic, no serial section.
// ---------------------------------------------------------------------------
__global__ __launch_bounds__(32 * 2 * BPB, 1) void crf_forward(
    const float* __restrict__ em,    // [B, S, T]
    const float* __restrict__ mask,  // [B, S]
    const float* __restrict__ tr)    // [T, T]
{
    const int w    = threadIdx.x >> 5;
    const int lane = threadIdx.x & 31;
    const int pb   = w & 3;           // batch within block (and SMSP id)
    const int half = w >> 2;          // column half: 0 -> cols 0..31, 1 -> 32..63
    const int b    = blockIdx.x * BPB + pb;
    const int j    = half * 32 + lane;  // my column

    __shared__ __align__(16) float sb[BPB][2][Tn];  // double-buffered s
    __shared__ float2 mrow[BPB][Sn];                // (m, 1-m)
    __shared__ float  fin[BPB][2];

    // Stage mask rows for the block's 4 batches (all 256 threads)
    for (int i = threadIdx.x; i < BPB * Sn; i += 32 * 2 * BPB) {
        int bb = i >> 10, tt = i & (Sn - 1);
        float m = mask[(blockIdx.x * BPB + bb) * Sn + tt];
        mrow[bb][tt] = make_float2(m, 1.0f - m);
    }

    // E column in registers: Ereg[p] = (E[2p][j], E[2p+1][j])
    u64 Ereg[32];
#pragma unroll
    for (int p = 0; p < 32; p++) {
        Ereg[p] = pk2(__expf(tr[(2 * p) * Tn + j]),
                      __expf(tr[(2 * p + 1) * Tn + j]));
    }

    // Emission pipeline for column j: raw 8 steps ahead, exp 2 ahead
    const float* ep = em + (size_t)b * Sn * Tn + j;
    float eraw[8];
#pragma unroll
    for (int d = 0; d < 8; d++) eraw[d] = __ldg(ep + d * Tn);
    float fb[4];
    fb[0] = __expf(eraw[0]);
    fb[1] = __expf(eraw[1]);

    float s    = 1.0f;
    int   offk = 0;
    __syncthreads();   // mrow visible

    for (int tb = 0; tb < Sn; tb += 8) {
#pragma unroll
        for (int u = 0; u < 8; u++) {
            const int t   = tb + u;
            const int par = u & 1;

            // publish own column's s
            sb[pb][par][j] = s;

            // off-chain pipeline refills (overlap the barrier wait)
            fb[(u + 2) & 3] = __expf(eraw[(u + 2) & 7]);
            if (t + 8 < Sn) eraw[u] = __ldg(ep + (size_t)(t + 8) * Tn);

            __syncthreads();   // STS drained; full s vector visible

            // q[j] = sum_i s[i] * E[i][j] : 8 LDS.128 (u64x2), 32 FFMA2
            const u64* sv = (const u64*)&sb[pb][par][0];
            u64 a0 = 0, a1 = 0, a2 = 0, a3 = 0;
            u64 v0;
#pragma unroll
            for (int p = 0; p < 32; p += 4) {
                ulonglong2 x = *(const ulonglong2*)&sv[p];
                ulonglong2 y = *(const ulonglong2*)&sv[p + 2];
                if (p == 0) v0 = x.x;
                a0 = ffma2(x.x, Ereg[p + 0], a0);
                a1 = ffma2(x.y, Ereg[p + 1], a1);
                a2 = ffma2(y.x, Ereg[p + 2], a2);
                a3 = ffma2(y.y, Ereg[p + 3], a3);
            }
            u64 aa = fadd2(fadd2(a0, a1), fadd2(a2, a3));
            float2 pq = upk(aa);
            float q = pq.x + pq.y;

            // masked blend: s = m * (q * f) + (1-m) * s
            float2 mm = mrow[pb][t];
            float sn = fmaf(mm.x, q * fb[u & 3], mm.y * s);

            // renorm every 8 steps by 2^-ke, ke from exponent of s[0]
            // (v0.x = published s[0], identical across the pair's 64 threads)
            if (u == 7) {
                int ke = ((__float_as_int(upk(v0).x) >> 23) & 0xff) - 127;
                offk += ke;
                sn *= __int_as_float((127 - ke) << 23);
            }
            s = sn;
        }
    }

    // z[b] = offk*ln2 + log(sum_j s[j])
    float x = s;
#pragma unroll
    for (int o = 16; o; o >>= 1)
        x += __shfl_xor_sync(0xffffffffu, x, o);
    if (lane == 0) fin[pb][half] = x;
    __syncthreads();
    if (w < BPB && lane == 0) {
        double z = (double)offk * 0.6931471805599453
                 + (double)logf(fin[w][0] + fin[w][1]);
        g_z[blockIdx.x * BPB + w] = (float)z;
    }
}

// ---------------------------------------------------------------------------
// Gold path scores
// ---------------------------------------------------------------------------
__global__ __launch_bounds__(256) void crf_gold(
    const float* __restrict__ em,
    const int*   __restrict__ tags,
    const float* __restrict__ mask,
    const float* __restrict__ tr)
{
    __shared__ float red[256];
    const int b   = blockIdx.x;
    const int tid = threadIdx.x;

    const int* tg = tags + b * Sn;
    float acc = 0.0f;
    for (int s = 1 + tid; s < Sn; s += 256) {
        int   t1  = tg[s];
        int   t0  = tg[s - 1];
        float mt  = mask[b * Sn + s];
        float emv = __ldg(em + (size_t)b * Sn * Tn + (size_t)s * Tn + t1);
        float trv = tr[t0 * Tn + t1];
        acc += (emv + trv) * mt;
    }
    red[tid] = acc;
    __syncthreads();
    for (int st = 128; st; st >>= 1) {
        if (tid < st) red[tid] += red[tid + st];
        __syncthreads();
    }
    if (tid == 0) g_sc[b] = red[0];
}

// ---------------------------------------------------------------------------
// out = -mean(z - score)
// ---------------------------------------------------------------------------
__global__ __launch_bounds__(Bn) void crf_final(float* __restrict__ out)
{
    __shared__ float red[Bn];
    const int tid = threadIdx.x;
    red[tid] = g_z[tid] - g_sc[tid];
    __syncthreads();
    for (int st = Bn / 2; st; st >>= 1) {
        if (tid < st) red[tid] += red[tid + st];
        __syncthreads();
    }
    if (tid == 0) out[0] = -red[0] / (float)Bn;
}

extern "C" void kernel_launch(void* const* d_in, const int* in_sizes, int n_in,
                              void* d_out, int out_size)
{
    const float* em   = (const float*)d_in[0];  // emissions [B,S,T] f32
    const int*   tags = (const int*)  d_in[1];  // tags [B,S] i32
    const float* mask = (const float*)d_in[2];  // mask [B,S] f32
    const float* tr   = (const float*)d_in[3];  // transitions [T,T] f32

    crf_forward<<<Bn / BPB, 32 * 2 * BPB>>>(em, mask, tr);
    crf_gold<<<Bn, 256>>>(em, tags, mask, tr);
    crf_final<<<1, Bn>>>((float*)d_out);
}

// round 6
// speedup vs baseline: 1.1020x; 1.1020x over previous
#include <cuda_runtime.h>
#include <cstdint>

// Problem shape (fixed by the dataset): B=512, S=1024, T=64
#define Bn 512
#define Sn 1024
#define Tn 64
#define BPB 4   // batches per block: forward warps 0-3 (one per SMSP),
                // gold warps 4-7 (retire early)

typedef unsigned long long u64;

__device__ float g_z[Bn];
__device__ float g_sc[Bn];

__device__ __forceinline__ u64 ffma2(u64 a, u64 b, u64 c) {
    u64 d;
    asm("fma.rn.f32x2 %0, %1, %2, %3;" : "=l"(d) : "l"(a), "l"(b), "l"(c));
    return d;
}
__device__ __forceinline__ u64 fadd2(u64 a, u64 b) {
    u64 d;
    asm("add.rn.f32x2 %0, %1, %2;" : "=l"(d) : "l"(a), "l"(b));
    return d;
}
__device__ __forceinline__ u64 fmul2(u64 a, u64 b) {
    u64 d;
    asm("mul.rn.f32x2 %0, %1, %2;" : "=l"(d) : "l"(a), "l"(b));
    return d;
}
__device__ __forceinline__ u64 pk2(float a, float b) {
    u64 d;
    asm("mov.b64 %0, {%1,%2};" : "=l"(d) : "f"(a), "f"(b));
    return d;
}
__device__ __forceinline__ float2 upk(u64 p) {
    float2 r;
    asm("mov.b64 {%0,%1}, %2;" : "=f"(r.x), "=f"(r.y) : "l"(p));
    return r;
}

// ---------------------------------------------------------------------------
// Fused forward recursion + gold scores.
// Forward (warps 0-3, one batch per warp per SMSP), linear domain:
//   s_{t+1}[j] = (sum_i s_t[i] * E[i][j]) * exp(e_t[j]),  E = exp(trans)
// Thread c owns columns (2c, 2c+1). Per step: publish s pair (STS.64),
// independent refills fill the sync window, 16 back-to-back LDS.128, 64 FFMA2.
// Renorm every 8 steps by 2^-ke from the exponent bits of s[0].
// Gold (warps 4-7): one warp per batch computes the tag-path score, then
// retires — its latency-bound gathers fill forward-warp stall slots.
// ---------------------------------------------------------------------------
__global__ __launch_bounds__(256, 1) void crf_fused(
    const float* __restrict__ em,    // [B, S, T]
    const int*   __restrict__ tags,  // [B, S]
    const float* __restrict__ mask,  // [B, S]
    const float* __restrict__ tr)    // [T, T]
{
    const int w    = threadIdx.x >> 5;
    const int lane = threadIdx.x & 31;

    __shared__ __align__(16) u64 sbuf[BPB][2][32];  // double-buffered s pairs
    __shared__ float2 mrow[BPB][Sn];                // (m, 1-m)

    // Stage mask rows for the block's 4 batches (all 8 warps help)
    for (int i = threadIdx.x; i < BPB * Sn; i += 256) {
        int bb = i >> 10, tt = i & (Sn - 1);
        float m = mask[(blockIdx.x * BPB + bb) * Sn + tt];
        mrow[bb][tt] = make_float2(m, 1.0f - m);
    }
    __syncthreads();

    if (w >= BPB) {
        // ------------------- gold warp: batch w-4 -------------------
        const int pb = w - BPB;
        const int b  = blockIdx.x * BPB + pb;
        const int* tg = tags + b * Sn;
        const float* eb = em + (size_t)b * Sn * Tn;
        float acc = 0.0f;
        for (int sx = 1 + lane; sx < Sn; sx += 32) {
            int   t1  = __ldg(tg + sx);
            int   t0  = __ldg(tg + sx - 1);
            float mt  = mrow[pb][sx].x;
            float emv = __ldg(eb + (size_t)sx * Tn + t1);
            float trv = __ldg(tr + t0 * Tn + t1);
            acc += (emv + trv) * mt;
        }
#pragma unroll
        for (int o = 16; o; o >>= 1)
            acc += __shfl_xor_sync(0xffffffffu, acc, o);
        if (lane == 0) g_sc[b] = acc;
        return;
    }

    // ------------------- forward warp: batch w -------------------
    const int pb = w;
    const int c  = lane;                       // column pair (2c, 2c+1)
    const int b  = blockIdx.x * BPB + pb;

    // E register tiles: EA[p] = (E[2p][2c], E[2p+1][2c]), EB for col 2c+1
    u64 EA[32], EB[32];
#pragma unroll
    for (int p = 0; p < 32; p++) {
        EA[p] = pk2(__expf(tr[(2 * p) * Tn + 2 * c]),
                    __expf(tr[(2 * p + 1) * Tn + 2 * c]));
        EB[p] = pk2(__expf(tr[(2 * p) * Tn + 2 * c + 1]),
                    __expf(tr[(2 * p + 1) * Tn + 2 * c + 1]));
    }

    // Emission pipeline: raw float2 loaded 8 steps ahead, exp'd 2 ahead
    const float2* ep = (const float2*)(em + (size_t)b * Sn * Tn) + c;
    float2 eraw[8];
    u64    fbuf[4];
#pragma unroll
    for (int d = 0; d < 8; d++) eraw[d] = __ldg(ep + d * 32);
    fbuf[0] = pk2(__expf(eraw[0].x), __expf(eraw[0].y));
    fbuf[1] = pk2(__expf(eraw[1].x), __expf(eraw[1].y));

    u64 s    = pk2(1.0f, 1.0f);
    int offk = 0;

    for (int tb = 0; tb < Sn; tb += 8) {
#pragma unroll
        for (int u = 0; u < 8; u++) {
            const int t   = tb + u;
            const int par = u & 1;

            // publish own pair
            sbuf[pb][par][c] = s;

            // independent work fills the sync window:
            float2 mm = mrow[pb][t];                       // mask for this step
            fbuf[(u + 2) & 3] =                             // exp 2 ahead
                pk2(__expf(eraw[(u + 2) & 7].x), __expf(eraw[(u + 2) & 7].y));
            if (t + 8 < Sn)                                 // reload 8 ahead
                eraw[u] = __ldg(ep + (size_t)(t + 8) * 32);

            __syncwarp();

            // 16 back-to-back LDS.128 (full s vector), then FFMA2 stream
            const ulonglong2* sv = (const ulonglong2*)&sbuf[pb][par][0];
            ulonglong2 x[16];
#pragma unroll
            for (int p = 0; p < 16; p++) x[p] = sv[p];

            u64 a0 = 0, a1 = 0, a2 = 0, a3 = 0;
            u64 b0 = 0, b1 = 0, b2 = 0, b3 = 0;
#pragma unroll
            for (int p = 0; p < 16; p += 2) {
                a0 = ffma2(x[p].x,     EA[2 * p + 0], a0);
                b0 = ffma2(x[p].x,     EB[2 * p + 0], b0);
                a1 = ffma2(x[p].y,     EA[2 * p + 1], a1);
                b1 = ffma2(x[p].y,     EB[2 * p + 1], b1);
                a2 = ffma2(x[p + 1].x, EA[2 * p + 2], a2);
                b2 = ffma2(x[p + 1].x, EB[2 * p + 2], b2);
                a3 = ffma2(x[p + 1].y, EA[2 * p + 3], a3);
                b3 = ffma2(x[p + 1].y, EB[2 * p + 3], b3);
            }
            u64 sa = fadd2(fadd2(a0, a1), fadd2(a2, a3));
            u64 sb = fadd2(fadd2(b0, b1), fadd2(b2, b3));
            float2 fa = upk(sa), fb2 = upk(sb);
            u64 qf = fmul2(pk2(fa.x + fa.y, fb2.x + fb2.y), fbuf[u & 3]);

            // masked blend: s = m*qf + (1-m)*s
            u64 sn = ffma2(pk2(mm.y, mm.y), s, fmul2(pk2(mm.x, mm.x), qf));

            // renorm every 8 steps by 2^-ke, ke from exponent of s[0]
            // (x[0].x = published s[0] pair, uniform across lanes)
            if (u == 7) {
                int ke = ((__float_as_int(upk(x[0].x).x) >> 23) & 0xff) - 127;
                offk += ke;
                float sc = __int_as_float((127 - ke) << 23);
                sn = fmul2(sn, pk2(sc, sc));
            }
            s = sn;
        }
    }

    // z[b] = offk*ln2 + log(sum_j s[j])
    float2 sp = upk(s);
    float x = sp.x + sp.y;
#pragma unroll
    for (int o = 16; o; o >>= 1)
        x += __shfl_xor_sync(0xffffffffu, x, o);
    if (lane == 0) {
        double z = (double)offk * 0.6931471805599453 + (double)logf(x);
        g_z[b] = (float)z;
    }
}

// ---------------------------------------------------------------------------
// out = -mean(z - score)
// ---------------------------------------------------------------------------
__global__ __launch_bounds__(Bn) void crf_final(float* __restrict__ out)
{
    __shared__ float red[Bn];
    const int tid = threadIdx.x;
    red[tid] = g_z[tid] - g_sc[tid];
    __syncthreads();
    for (int st = Bn / 2; st; st >>= 1) {
        if (tid < st) red[tid] += red[tid + st];
        __syncthreads();
    }
    if (tid == 0) out[0] = -red[0] / (float)Bn;
}

extern "C" void kernel_launch(void* const* d_in, const int* in_sizes, int n_in,
                              void* d_out, int out_size)
{
    const float* em   = (const float*)d_in[0];  // emissions [B,S,T] f32
    const int*   tags = (const int*)  d_in[1];  // tags [B,S] i32
    const float* mask = (const float*)d_in[2];  // mask [B,S] f32
    const float* tr   = (const float*)d_in[3];  // transitions [T,T] f32

    crf_fused<<<Bn / BPB, 256>>>(em, tags, mask, tr);
    crf_final<<<1, Bn>>>((float*)d_out);
}

// round 9
// speedup vs baseline: 1.2449x; 1.1297x over previous
#include <cuda_runtime.h>
#include <cstdint>

// Problem shape (fixed by the dataset): B=512, S=1024, T=64
#define Bn 512
#define Sn 1024
#define Tn 64
#define BPB 4          // forward batches per block (warp pairs)
#define FWD_BLOCKS 128 // blocks 0..127: forward; 128..143: gold
#define GOLD_BLOCKS 16

typedef unsigned long long u64;

__device__ float g_z[Bn];
__device__ float g_sc[Bn];

__device__ __forceinline__ u64 ffma2(u64 a, u64 b, u64 c) {
    u64 d;
    asm("fma.rn.f32x2 %0, %1, %2, %3;" : "=l"(d) : "l"(a), "l"(b), "l"(c));
    return d;
}
__device__ __forceinline__ u64 fadd2(u64 a, u64 b) {
    u64 d;
    asm("add.rn.f32x2 %0, %1, %2;" : "=l"(d) : "l"(a), "l"(b));
    return d;
}
__device__ __forceinline__ u64 pk2(float a, float b) {
    u64 d;
    asm("mov.b64 %0, {%1,%2};" : "=l"(d) : "f"(a), "f"(b));
    return d;
}
__device__ __forceinline__ float2 upk(u64 p) {
    float2 r;
    asm("mov.b64 {%0,%1}, %2;" : "=f"(r.x), "=f"(r.y) : "l"(p));
    return r;
}
__device__ __forceinline__ void bar_pair(int id) {
    asm volatile("bar.sync %0, 64;" :: "r"(id) : "memory");
}

// ---------------------------------------------------------------------------
// Forward recursion (blocks 0..127), linear domain:
//   s_{t+1}[j] = (sum_i s_t[i] * E[i][j]) * exp(e_t[j]),  E = exp(trans)
// Batch p is owned by warp pair (2p, 2p+1) — consecutive warp ids land on
// DIFFERENT SMSPs; each SMSP hosts warps of two different pairs so one
// pair's barrier wait is covered by the other pair's compute. Each warp owns
// 32 columns (1 col/thread): full 64-term contraction = 16 LDS.128 + 32 FFMA2.
// Renorm every 8 steps by 2^-ke from the exponent bits of s[0].
// Gold scores (blocks 128..143) run on the SMs the forward grid leaves idle.
// ---------------------------------------------------------------------------
__global__ __launch_bounds__(256, 1) void crf_fused(
    const float* __restrict__ em,    // [B, S, T]
    const int*   __restrict__ tags,  // [B, S]
    const float* __restrict__ mask,  // [B, S]
    const float* __restrict__ tr)    // [T, T]
{
    const int w    = threadIdx.x >> 5;
    const int lane = threadIdx.x & 31;

    if (blockIdx.x >= FWD_BLOCKS) {
        // ---------------- gold blocks: 8 warps, 4 batches per warp --------
        const int gw = (blockIdx.x - FWD_BLOCKS) * 8 + w;   // 0..127
        for (int k = 0; k < 4; k++) {
            const int b = gw * 4 + k;
            const int* tg = tags + b * Sn;
            const float* eb = em + (size_t)b * Sn * Tn;
            float acc = 0.0f;
            for (int sx = 1 + lane; sx < Sn; sx += 32) {
                int   t1  = __ldg(tg + sx);
                int   t0  = __ldg(tg + sx - 1);
                float mt  = __ldg(mask + b * Sn + sx);
                float emv = __ldg(eb + (size_t)sx * Tn + t1);
                float trv = __ldg(tr + t0 * Tn + t1);
                acc += (emv + trv) * mt;
            }
#pragma unroll
            for (int o = 16; o; o >>= 1)
                acc += __shfl_xor_sync(0xffffffffu, acc, o);
            if (lane == 0) g_sc[b] = acc;
        }
        return;
    }

    // ---------------- forward blocks ----------------
    const int p    = w >> 1;            // batch within block (pair id)
    const int half = w & 1;             // column half
    const int b    = blockIdx.x * BPB + p;
    const int j    = half * 32 + lane;  // my column

    __shared__ __align__(16) float sbuf[BPB][2][Tn];  // double-buffered s
    __shared__ float2 mrow[BPB][Sn];                  // (m, 1-m)
    __shared__ float  fin[BPB][2];

    for (int i = threadIdx.x; i < BPB * Sn; i += 256) {
        int bb = i >> 10, tt = i & (Sn - 1);
        float m = mask[(blockIdx.x * BPB + bb) * Sn + tt];
        mrow[bb][tt] = make_float2(m, 1.0f - m);
    }

    // E column in registers: Ereg[q] = (E[2q][j], E[2q+1][j]), q = 0..31
    u64 Ereg[32];
#pragma unroll
    for (int q = 0; q < 32; q++) {
        Ereg[q] = pk2(__expf(tr[(2 * q) * Tn + j]),
                      __expf(tr[(2 * q + 1) * Tn + j]));
    }

    // Emission pipeline for column j: raw 8 steps ahead, exp 2 ahead
    const float* ep = em + (size_t)b * Sn * Tn + j;
    float eraw[8];
#pragma unroll
    for (int d = 0; d < 8; d++) eraw[d] = __ldg(ep + d * Tn);
    float fb[4];
    fb[0] = __expf(eraw[0]);
    fb[1] = __expf(eraw[1]);

    float s    = 1.0f;
    int   offk = 0;
    __syncthreads();   // mrow visible (all 8 forward warps)

    for (int tb = 0; tb < Sn; tb += 8) {
#pragma unroll
        for (int u = 0; u < 8; u++) {
            const int t   = tb + u;
            const int par = u & 1;

            // publish own column
            sbuf[p][par][j] = s;

            // independent work fills the barrier window
            float2 mm = mrow[p][t];
            fb[(u + 2) & 3] = __expf(eraw[(u + 2) & 7]);
            if (t + 8 < Sn) eraw[u] = __ldg(ep + (size_t)(t + 8) * Tn);

            bar_pair(1 + p);   // pair-wide: STS drained, full s visible

            // FULL contraction: 16 LDS.128 (all 64 s values), 32 FFMA2
            const float4* sv4 = (const float4*)&sbuf[p][par][0];
            float4 xv[16];
#pragma unroll
            for (int q = 0; q < 16; q++) xv[q] = sv4[q];

            u64 a0 = 0, a1 = 0, a2 = 0, a3 = 0;
#pragma unroll
            for (int q = 0; q < 16; q += 2) {
                const ulonglong2* x0 = (const ulonglong2*)&xv[q];
                const ulonglong2* x1 = (const ulonglong2*)&xv[q + 1];
                a0 = ffma2(x0->x, Ereg[2 * q + 0], a0);
                a1 = ffma2(x0->y, Ereg[2 * q + 1], a1);
                a2 = ffma2(x1->x, Ereg[2 * q + 2], a2);
                a3 = ffma2(x1->y, Ereg[2 * q + 3], a3);
            }
            u64 aa = fadd2(fadd2(a0, a1), fadd2(a2, a3));
            float2 pq = upk(aa);
            float qv = pq.x + pq.y;

            // masked blend: s = m*(q*f) + (1-m)*s
            float sn = fmaf(mm.x, qv * fb[u & 3], mm.y * s);

            // renorm every 8 steps by 2^-ke, ke from exponent of s[0]
            if (u == 7) {
                int ke = ((__float_as_int(xv[0].x) >> 23) & 0xff) - 127;
                offk += ke;
                sn *= __int_as_float((127 - ke) << 23);
            }
            s = sn;
        }
    }

    // z[b] = offk*ln2 + log(sum_j s[j]) — written by each pair's half-0 warp
    // (its offk belongs to batch p)
    float x = s;
#pragma unroll
    for (int o = 16; o; o >>= 1)
        x += __shfl_xor_sync(0xffffffffu, x, o);
    if (lane == 0) fin[p][half] = x;
    __syncthreads();
    if (half == 0 && lane == 0) {
        double z = (double)offk * 0.6931471805599453
                 + (double)logf(fin[p][0] + fin[p][1]);
        g_z[b] = (float)z;
    }
}

// ---------------------------------------------------------------------------
// out = -mean(z - score)
// ---------------------------------------------------------------------------
__global__ __launch_bounds__(Bn) void crf_final(float* __restrict__ out)
{
    __shared__ float red[Bn];
    const int tid = threadIdx.x;
    red[tid] = g_z[tid] - g_sc[tid];
    __syncthreads();
    for (int st = Bn / 2; st; st >>= 1) {
        if (tid < st) red[tid] += red[tid + st];
        __syncthreads();
    }
    if (tid == 0) out[0] = -red[0] / (float)Bn;
}

extern "C" void kernel_launch(void* const* d_in, const int* in_sizes, int n_in,
                              void* d_out, int out_size)
{
    const float* em   = (const float*)d_in[0];  // emissions [B,S,T] f32
    const int*   tags = (const int*)  d_in[1];  // tags [B,S] i32
    const float* mask = (const float*)d_in[2];  // mask [B,S] f32
    const float* tr   = (const float*)d_in[3];  // transitions [T,T] f32

    crf_fused<<<FWD_BLOCKS + GOLD_BLOCKS, 256>>>(em, tags, mask, tr);
    crf_final<<<1, Bn>>>((float*)d_out);
}